// round 16
// baseline (speedup 1.0000x reference)
#include <cuda_runtime.h>
#include <cuda_bf16.h>
#include <cuda_fp16.h>
#include <math.h>
#include <stdint.h>

#define N_NODES   8192
#define C_IN      256
#define C_OUT     128
#define NEG_SLOPE 0.2f
#define MAX_DEG   128

#define BM 32
#define BK 16
#define GEMM_BLOCKS (N_NODES / BM)     // 256
#define SCAN_BLOCKS 2048
#define BLOCK_U4    8192               // 128KB contiguous per scan block
#define QCAP        256                // per-warp queue capacity (mean ~16)

// -------- scratch (__device__ globals; zero-initialized at module load) ----
__device__ float  g_h[N_NODES * C_OUT];      // 4 MB fp32 (self-loop + scores)
__device__ __half g_h16[N_NODES * C_OUT];    // 2 MB fp16 (edge gathers)
__device__ float  g_asrc[N_NODES];
__device__ float  g_adst[N_NODES];
__device__ int    g_cnt[N_NODES];            // per-column degree (excl. self)
__device__ int    g_list[N_NODES * MAX_DEG]; // 4 MB, CSC row lists

#define FULLM 0xFFFFFFFFu

// bit-cast helpers
__device__ __forceinline__ unsigned int h2_to_u32(__half2 h) {
    return *reinterpret_cast<unsigned int*>(&h);
}
__device__ __forceinline__ __half2 u32_to_h2(unsigned int u) {
    return *reinterpret_cast<__half2*>(&u);
}

// ---------------------------------------------------------------------
// Fused front kernel (FROZEN — R14 configuration, best measured).
//  blocks [0, GEMM_BLOCKS):            h = x@W (4x4 micro-tile) + attn scores;
//                                      epilogue also writes fp16 copy of h.
//  blocks [GEMM_BLOCKS, +SCAN_BLOCKS): stream adj once; nonzeros go through
//    a per-warp smem queue (ATOMS ~30cyc) instead of ATOMG+dependent STG,
//    drained lane-parallel after the stream.
// g_cnt is zeroed by the previous aggregate launch (zero-init at load).
// ---------------------------------------------------------------------
__global__ __launch_bounds__(256, 6) void fused_front_kernel(
    const float* __restrict__ x, const float* __restrict__ W,
    const float* __restrict__ adj,
    const float* __restrict__ att_src, const float* __restrict__ att_dst) {

    __shared__ union USm {
        struct { float xs[BK][BM]; float ws[BK][C_OUT]; } g;   // 10 KB
        struct { unsigned int q[8][QCAP]; int qcnt[8]; } s;    // 8 KB + 32B
    } su;

    int tid = threadIdx.x;

    if (blockIdx.x >= GEMM_BLOCKS) {
        // ======= adjacency scan: contiguous chunk, batch-4 LDG.128 =======
        const uint4* a4 = reinterpret_cast<const uint4*>(adj);
        const int sb   = blockIdx.x - GEMM_BLOCKS;
        const int base = sb * BLOCK_U4;          // contiguous 8192-uint4 chunk
        const int w    = tid >> 5;
        const int lane = tid & 31;

        if (lane == 0) su.s.qcnt[w] = 0;
        __syncwarp();

#pragma unroll
        for (int it = 0; it < 8; it++) {
            int qb = base + it * 1024 + tid;     // iter consumes 1024 uint4
            uint4 v0 = __ldcs(&a4[qb]);
            uint4 v1 = __ldcs(&a4[qb + 256]);
            uint4 v2 = __ldcs(&a4[qb + 512]);
            uint4 v3 = __ldcs(&a4[qb + 768]);
            uint4 vv[4] = {v0, v1, v2, v3};
#pragma unroll
            for (int u = 0; u < 4; u++) {
                uint4 v = vv[u];
                if ((v.x | v.y | v.z | v.w) == 0u) continue;
                int Q  = qb + u * 256;
                int i  = Q >> 11;                 // row (2048 uint4 per row)
                int j0 = (Q & 2047) << 2;         // first column of the 4
                unsigned int b[4] = {v.x, v.y, v.z, v.w};
#pragma unroll
                for (int t = 0; t < 4; t++) {
                    if (b[t] != 0u) {
                        int jj = j0 + t;
                        if (jj != i) {            // diagonal handled in aggregate
                            int p = atomicAdd(&su.s.qcnt[w], 1);   // smem, ~30cyc
                            if (p < QCAP) {
                                su.s.q[w][p] = ((unsigned)i << 13) | (unsigned)jj;
                            } else {              // overflow fallback (cold)
                                int pos = atomicAdd(&g_cnt[jj], 1);
                                if (pos < MAX_DEG) g_list[jj * MAX_DEG + pos] = i;
                            }
                        }
                    }
                }
            }
        }
        __syncwarp();

        // ---- drain: lane-parallel independent ATOMG + STG ----
        int n = su.s.qcnt[w];
        if (n > QCAP) n = QCAP;
        for (int e = lane; e < n; e += 32) {
            unsigned int v = su.s.q[w][e];
            int jj = v & 8191u;
            int i  = v >> 13;
            int pos = atomicAdd(&g_cnt[jj], 1);
            if (pos < MAX_DEG) g_list[jj * MAX_DEG + pos] = i;
        }
        return;
    }

    // ================= GEMM (BM=32, 4x4 micro-tile) + attention =================
    int row0 = blockIdx.x * BM;
    int tx = tid & 31;   // channel group: c = tx*4
    int ty = tid >> 5;   // row group: rows ty*4 .. ty*4+3 (warp == fixed ty)

    float acc[4][4];
#pragma unroll
    for (int r = 0; r < 4; r++)
#pragma unroll
        for (int c = 0; c < 4; c++) acc[r][c] = 0.0f;

    for (int k0 = 0; k0 < C_IN; k0 += BK) {
        {   // x tile: 32 rows x 16 k, one float2 per thread
            int r  = tid >> 3;          // 0..31
            int kk = (tid & 7) * 2;     // 0,2,..,14
            float2 v = *reinterpret_cast<const float2*>(
                &x[(row0 + r) * C_IN + k0 + kk]);
            su.g.xs[kk + 0][r] = v.x; su.g.xs[kk + 1][r] = v.y;
        }
        {   // W tile: 16 k x 128 c, two float4 per thread
            int kk = tid >> 5;              // 0..7
            int c  = (tid & 31) * 4;
            *reinterpret_cast<float4*>(&su.g.ws[kk][c]) =
                *reinterpret_cast<const float4*>(&W[(k0 + kk) * C_OUT + c]);
            *reinterpret_cast<float4*>(&su.g.ws[kk + 8][c]) =
                *reinterpret_cast<const float4*>(&W[(k0 + kk + 8) * C_OUT + c]);
        }
        __syncthreads();
#pragma unroll
        for (int kk = 0; kk < BK; kk++) {
            float4 b = *reinterpret_cast<const float4*>(&su.g.ws[kk][tx * 4]);
#pragma unroll
            for (int r = 0; r < 4; r++) {
                float a = su.g.xs[kk][ty * 4 + r];
                acc[r][0] += a * b.x;
                acc[r][1] += a * b.y;
                acc[r][2] += a * b.z;
                acc[r][3] += a * b.w;
            }
        }
        __syncthreads();
    }

    float4 as = *reinterpret_cast<const float4*>(&att_src[tx * 4]);
    float4 ad = *reinterpret_cast<const float4*>(&att_dst[tx * 4]);

#pragma unroll
    for (int r = 0; r < 4; r++) {
        int row = row0 + ty * 4 + r;
        float4 v = make_float4(acc[r][0], acc[r][1], acc[r][2], acc[r][3]);
        *reinterpret_cast<float4*>(&g_h[row * C_OUT + tx * 4]) = v;

        // fp16 copy for the aggregate's edge gathers (halves L2 bytes)
        uint2 packed;
        packed.x = h2_to_u32(__floats2half2_rn(v.x, v.y));
        packed.y = h2_to_u32(__floats2half2_rn(v.z, v.w));
        *reinterpret_cast<uint2*>(&g_h16[row * C_OUT + tx * 4]) = packed;

        float s = v.x * as.x + v.y * as.y + v.z * as.z + v.w * as.w;
        float d = v.x * ad.x + v.y * ad.y + v.z * ad.z + v.w * ad.w;
#pragma unroll
        for (int o = 16; o > 0; o >>= 1) {
            s += __shfl_xor_sync(FULLM, s, o);
            d += __shfl_xor_sync(FULLM, d, o);
        }
        if (tx == 0) { g_asrc[row] = s; g_adst[row] = d; }
    }
}

// ---------------------------------------------------------------------
// Aggregate: one WARP per column; NO shfl broadcasts. Prologue writes
// (ew, idx) pairs to a per-warp smem table once; the main loop reads
// them via uniform-address LDS.64 broadcasts (independent, hoistable)
// and issues 8 fp16 row-gathers in flight per step. Flat edge loop,
// fewer registers than the shfl version. fp32 accumulation.
// Resets g_cnt for the next graph replay.
// ---------------------------------------------------------------------
__device__ __forceinline__ void fma_h16(float4& acc, float e, uint2 p) {
    float2 flo = __half22float2(u32_to_h2(p.x));
    float2 fhi = __half22float2(u32_to_h2(p.y));
    acc.x += e * flo.x; acc.y += e * flo.y;
    acc.z += e * fhi.x; acc.w += e * fhi.y;
}

__global__ __launch_bounds__(256) void aggregate_kernel(
    const float* __restrict__ bias, float* __restrict__ out) {
    __shared__ float2 sq[8][MAX_DEG];     // (ew, idx-as-float-bits), 8 KB

    int w    = threadIdx.x >> 5;
    int lane = threadIdx.x & 31;
    int j    = blockIdx.x * 8 + w;        // column

    int cnt = g_cnt[j];
    if (cnt > MAX_DEG) cnt = MAX_DEG;
    float adst_j = g_adst[j];

    // prologue: compute exp-weights, fill smem table, partial sum
    float partial = 0.0f;
    for (int d = lane; d < cnt; d += 32) {
        int i = g_list[j * MAX_DEG + d];
        float z = g_asrc[i] + adst_j;
        z = (z > 0.0f) ? z : NEG_SLOPE * z;
        float e = __expf(z);
        sq[w][d] = make_float2(e, __int_as_float(i));
        partial += e;
    }
    __syncwarp();
    if (lane == 0) g_cnt[j] = 0;          // reset for next graph replay

#pragma unroll
    for (int o = 16; o > 0; o >>= 1) partial += __shfl_xor_sync(FULLM, partial, o);

    // self-loop (reference SETS the diagonal to 1 -> always present), fp32
    float zs = g_asrc[j] + adst_j;
    zs = (zs > 0.0f) ? zs : NEG_SLOPE * zs;
    float es  = __expf(zs);
    float inv = 1.0f / (partial + es);

    float4 h0 = reinterpret_cast<const float4*>(&g_h[j * C_OUT])[lane];
    float4 acc0 = make_float4(es * h0.x, es * h0.y, es * h0.z, es * h0.w);
    float4 acc1 = make_float4(0.f, 0.f, 0.f, 0.f);

    const uint2* h16 = reinterpret_cast<const uint2*>(g_h16);   // 32 uint2/row

    int d = 0;
    for (; d + 8 <= cnt; d += 8) {
        float2 q0 = sq[w][d];     float2 q1 = sq[w][d + 1];
        float2 q2 = sq[w][d + 2]; float2 q3 = sq[w][d + 3];
        float2 q4 = sq[w][d + 4]; float2 q5 = sq[w][d + 5];
        float2 q6 = sq[w][d + 6]; float2 q7 = sq[w][d + 7];
        uint2 p0 = h16[__float_as_int(q0.y) * 32 + lane];
        uint2 p1 = h16[__float_as_int(q1.y) * 32 + lane];
        uint2 p2 = h16[__float_as_int(q2.y) * 32 + lane];
        uint2 p3 = h16[__float_as_int(q3.y) * 32 + lane];
        uint2 p4 = h16[__float_as_int(q4.y) * 32 + lane];
        uint2 p5 = h16[__float_as_int(q5.y) * 32 + lane];
        uint2 p6 = h16[__float_as_int(q6.y) * 32 + lane];
        uint2 p7 = h16[__float_as_int(q7.y) * 32 + lane];
        fma_h16(acc0, q0.x, p0);
        fma_h16(acc1, q1.x, p1);
        fma_h16(acc0, q2.x, p2);
        fma_h16(acc1, q3.x, p3);
        fma_h16(acc0, q4.x, p4);
        fma_h16(acc1, q5.x, p5);
        fma_h16(acc0, q6.x, p6);
        fma_h16(acc1, q7.x, p7);
    }
    for (; d < cnt; d++) {
        float2 q = sq[w][d];
        uint2 p = h16[__float_as_int(q.y) * 32 + lane];
        fma_h16(acc0, q.x, p);
    }

    float4 bv = reinterpret_cast<const float4*>(bias)[lane];
    float4 o;
    o.x = (acc0.x + acc1.x) * inv + bv.x;
    o.y = (acc0.y + acc1.y) * inv + bv.y;
    o.z = (acc0.z + acc1.z) * inv + bv.z;
    o.w = (acc0.w + acc1.w) * inv + bv.w;
    reinterpret_cast<float4*>(&out[j * C_OUT])[lane] = o;
}

// ---------------------------------------------------------------------
extern "C" void kernel_launch(void* const* d_in, const int* in_sizes, int n_in,
                              void* d_out, int out_size) {
    const float* x       = (const float*)d_in[0];
    const float* adj     = (const float*)d_in[1];
    const float* W       = (const float*)d_in[2];
    const float* att_src = (const float*)d_in[3];
    const float* att_dst = (const float*)d_in[4];
    const float* bias    = (const float*)d_in[5];
    float* out = (float*)d_out;

    fused_front_kernel<<<GEMM_BLOCKS + SCAN_BLOCKS, 256>>>(x, W, adj, att_src, att_dst);
    aggregate_kernel<<<N_NODES / 8, 256>>>(bias, out);
}

// round 17
// speedup vs baseline: 1.0642x; 1.0642x over previous
#include <cuda_runtime.h>
#include <cuda_bf16.h>
#include <cuda_fp16.h>
#include <math.h>
#include <stdint.h>

#define N_NODES   8192
#define C_IN      256
#define C_OUT     128
#define NEG_SLOPE 0.2f
#define MAX_DEG   128

#define BM 32
#define BK 16
#define GEMM_BLOCKS (N_NODES / BM)     // 256
#define SCAN_BLOCKS 2048
#define BLOCK_U4    8192               // 128KB contiguous per scan block
#define QCAP        256                // per-warp queue capacity (mean ~16)

// -------- scratch (__device__ globals; zero-initialized at module load) ----
__device__ float  g_h[N_NODES * C_OUT];      // 4 MB fp32 (self-loop + scores)
__device__ __half g_h16[N_NODES * C_OUT];    // 2 MB fp16 (edge gathers)
__device__ float  g_asrc[N_NODES];
__device__ float  g_adst[N_NODES];
__device__ int    g_cnt[N_NODES];            // per-column degree (excl. self)
__device__ int    g_list[N_NODES * MAX_DEG]; // 4 MB, CSC row lists

#define FULLM 0xFFFFFFFFu

// bit-cast helpers
__device__ __forceinline__ unsigned int h2_to_u32(__half2 h) {
    return *reinterpret_cast<unsigned int*>(&h);
}
__device__ __forceinline__ __half2 u32_to_h2(unsigned int u) {
    return *reinterpret_cast<__half2*>(&u);
}

// ---------------------------------------------------------------------
// Fused front kernel (FROZEN — R14 configuration, best measured).
//  blocks [0, GEMM_BLOCKS):            h = x@W (4x4 micro-tile) + attn scores;
//                                      epilogue also writes fp16 copy of h.
//  blocks [GEMM_BLOCKS, +SCAN_BLOCKS): stream adj once; nonzeros go through
//    a per-warp smem queue (ATOMS ~30cyc) instead of ATOMG+dependent STG,
//    drained lane-parallel after the stream.
// g_cnt is zeroed by the previous aggregate launch (zero-init at load).
// ---------------------------------------------------------------------
__global__ __launch_bounds__(256, 6) void fused_front_kernel(
    const float* __restrict__ x, const float* __restrict__ W,
    const float* __restrict__ adj,
    const float* __restrict__ att_src, const float* __restrict__ att_dst) {

    __shared__ union USm {
        struct { float xs[BK][BM]; float ws[BK][C_OUT]; } g;   // 10 KB
        struct { unsigned int q[8][QCAP]; int qcnt[8]; } s;    // 8 KB + 32B
    } su;

    int tid = threadIdx.x;

    if (blockIdx.x >= GEMM_BLOCKS) {
        // ======= adjacency scan: contiguous chunk, batch-4 LDG.128 =======
        const uint4* a4 = reinterpret_cast<const uint4*>(adj);
        const int sb   = blockIdx.x - GEMM_BLOCKS;
        const int base = sb * BLOCK_U4;          // contiguous 8192-uint4 chunk
        const int w    = tid >> 5;
        const int lane = tid & 31;

        if (lane == 0) su.s.qcnt[w] = 0;
        __syncwarp();

#pragma unroll
        for (int it = 0; it < 8; it++) {
            int qb = base + it * 1024 + tid;     // iter consumes 1024 uint4
            uint4 v0 = __ldcs(&a4[qb]);
            uint4 v1 = __ldcs(&a4[qb + 256]);
            uint4 v2 = __ldcs(&a4[qb + 512]);
            uint4 v3 = __ldcs(&a4[qb + 768]);
            uint4 vv[4] = {v0, v1, v2, v3};
#pragma unroll
            for (int u = 0; u < 4; u++) {
                uint4 v = vv[u];
                if ((v.x | v.y | v.z | v.w) == 0u) continue;
                int Q  = qb + u * 256;
                int i  = Q >> 11;                 // row (2048 uint4 per row)
                int j0 = (Q & 2047) << 2;         // first column of the 4
                unsigned int b[4] = {v.x, v.y, v.z, v.w};
#pragma unroll
                for (int t = 0; t < 4; t++) {
                    if (b[t] != 0u) {
                        int jj = j0 + t;
                        if (jj != i) {            // diagonal handled in aggregate
                            int p = atomicAdd(&su.s.qcnt[w], 1);   // smem, ~30cyc
                            if (p < QCAP) {
                                su.s.q[w][p] = ((unsigned)i << 13) | (unsigned)jj;
                            } else {              // overflow fallback (cold)
                                int pos = atomicAdd(&g_cnt[jj], 1);
                                if (pos < MAX_DEG) g_list[jj * MAX_DEG + pos] = i;
                            }
                        }
                    }
                }
            }
        }
        __syncwarp();

        // ---- drain: lane-parallel independent ATOMG + STG ----
        int n = su.s.qcnt[w];
        if (n > QCAP) n = QCAP;
        for (int e = lane; e < n; e += 32) {
            unsigned int v = su.s.q[w][e];
            int jj = v & 8191u;
            int i  = v >> 13;
            int pos = atomicAdd(&g_cnt[jj], 1);
            if (pos < MAX_DEG) g_list[jj * MAX_DEG + pos] = i;
        }
        return;
    }

    // ================= GEMM (BM=32, 4x4 micro-tile) + attention =================
    int row0 = blockIdx.x * BM;
    int tx = tid & 31;   // channel group: c = tx*4
    int ty = tid >> 5;   // row group: rows ty*4 .. ty*4+3 (warp == fixed ty)

    float acc[4][4];
#pragma unroll
    for (int r = 0; r < 4; r++)
#pragma unroll
        for (int c = 0; c < 4; c++) acc[r][c] = 0.0f;

    for (int k0 = 0; k0 < C_IN; k0 += BK) {
        {   // x tile: 32 rows x 16 k, one float2 per thread
            int r  = tid >> 3;          // 0..31
            int kk = (tid & 7) * 2;     // 0,2,..,14
            float2 v = *reinterpret_cast<const float2*>(
                &x[(row0 + r) * C_IN + k0 + kk]);
            su.g.xs[kk + 0][r] = v.x; su.g.xs[kk + 1][r] = v.y;
        }
        {   // W tile: 16 k x 128 c, two float4 per thread
            int kk = tid >> 5;              // 0..7
            int c  = (tid & 31) * 4;
            *reinterpret_cast<float4*>(&su.g.ws[kk][c]) =
                *reinterpret_cast<const float4*>(&W[(k0 + kk) * C_OUT + c]);
            *reinterpret_cast<float4*>(&su.g.ws[kk + 8][c]) =
                *reinterpret_cast<const float4*>(&W[(k0 + kk + 8) * C_OUT + c]);
        }
        __syncthreads();
#pragma unroll
        for (int kk = 0; kk < BK; kk++) {
            float4 b = *reinterpret_cast<const float4*>(&su.g.ws[kk][tx * 4]);
#pragma unroll
            for (int r = 0; r < 4; r++) {
                float a = su.g.xs[kk][ty * 4 + r];
                acc[r][0] += a * b.x;
                acc[r][1] += a * b.y;
                acc[r][2] += a * b.z;
                acc[r][3] += a * b.w;
            }
        }
        __syncthreads();
    }

    float4 as = *reinterpret_cast<const float4*>(&att_src[tx * 4]);
    float4 ad = *reinterpret_cast<const float4*>(&att_dst[tx * 4]);

#pragma unroll
    for (int r = 0; r < 4; r++) {
        int row = row0 + ty * 4 + r;
        float4 v = make_float4(acc[r][0], acc[r][1], acc[r][2], acc[r][3]);
        *reinterpret_cast<float4*>(&g_h[row * C_OUT + tx * 4]) = v;

        // fp16 copy for the aggregate's edge gathers (halves L2 bytes)
        uint2 packed;
        packed.x = h2_to_u32(__floats2half2_rn(v.x, v.y));
        packed.y = h2_to_u32(__floats2half2_rn(v.z, v.w));
        *reinterpret_cast<uint2*>(&g_h16[row * C_OUT + tx * 4]) = packed;

        float s = v.x * as.x + v.y * as.y + v.z * as.z + v.w * as.w;
        float d = v.x * ad.x + v.y * ad.y + v.z * ad.z + v.w * ad.w;
#pragma unroll
        for (int o = 16; o > 0; o >>= 1) {
            s += __shfl_xor_sync(FULLM, s, o);
            d += __shfl_xor_sync(FULLM, d, o);
        }
        if (tx == 0) { g_asrc[row] = s; g_adst[row] = d; }
    }
}

// ---------------------------------------------------------------------
// Aggregate: TWO columns per warp, 128-thread blocks (4 warps = 8 cols),
// grid 1024 -> ~7 blocks/SM resident -> SINGLE WAVE (the 1.5-wave tail
// was the hidden 2x on every previous aggregate variant). Interleaved
// gather loop: 4 edges per column per step = 8 independent fp16 row
// gathers in flight. Edge lists padded to multiples of 4 with
// zero-weight entries so the per-column loops are branch-light.
// fp32 accumulation/self-loop/normalization. Resets g_cnt for replay.
// ---------------------------------------------------------------------
__device__ __forceinline__ void fma_h16(float4& acc, float e, uint2 p) {
    float2 flo = __half22float2(u32_to_h2(p.x));
    float2 fhi = __half22float2(u32_to_h2(p.y));
    acc.x += e * flo.x; acc.y += e * flo.y;
    acc.z += e * fhi.x; acc.w += e * fhi.y;
}

__global__ __launch_bounds__(128) void aggregate_kernel(
    const float* __restrict__ bias, float* __restrict__ out) {
    __shared__ float2 sq[8][MAX_DEG];     // (ew, idx-as-float-bits), 8 KB

    int w    = threadIdx.x >> 5;          // 0..3
    int lane = threadIdx.x & 31;
    int jA   = blockIdx.x * 8 + w * 2;    // this warp's two columns
    int jB   = jA + 1;
    int sA   = w * 2, sB = w * 2 + 1;     // smem table slots

    int cntA = g_cnt[jA]; if (cntA > MAX_DEG) cntA = MAX_DEG;
    int cntB = g_cnt[jB]; if (cntB > MAX_DEG) cntB = MAX_DEG;
    float adA = g_adst[jA];
    float adB = g_adst[jB];

    // prologue: exp-weights for both columns into smem + partial sums
    float pA = 0.0f, pB = 0.0f;
    for (int d = lane; d < cntA; d += 32) {
        int i = g_list[jA * MAX_DEG + d];
        float z = g_asrc[i] + adA;
        z = (z > 0.0f) ? z : NEG_SLOPE * z;
        float e = __expf(z);
        sq[sA][d] = make_float2(e, __int_as_float(i));
        pA += e;
    }
    for (int d = lane; d < cntB; d += 32) {
        int i = g_list[jB * MAX_DEG + d];
        float z = g_asrc[i] + adB;
        z = (z > 0.0f) ? z : NEG_SLOPE * z;
        float e = __expf(z);
        sq[sB][d] = make_float2(e, __int_as_float(i));
        pB += e;
    }
    // pad to multiple of 4 with zero-weight entries (row 0, weight 0)
    int cA4 = (cntA + 3) & ~3;
    int cB4 = (cntB + 3) & ~3;
    {
        int d = cntA + lane;
        if (d < cA4) sq[sA][d] = make_float2(0.0f, __int_as_float(0));
        d = cntB + lane;
        if (d < cB4) sq[sB][d] = make_float2(0.0f, __int_as_float(0));
    }
    __syncwarp();
    if (lane == 0) { g_cnt[jA] = 0; g_cnt[jB] = 0; }   // reset for replay

#pragma unroll
    for (int o = 16; o > 0; o >>= 1) {
        pA += __shfl_xor_sync(FULLM, pA, o);
        pB += __shfl_xor_sync(FULLM, pB, o);
    }

    // self-loops (reference SETS the diagonal to 1 -> always present)
    float zA = g_asrc[jA] + adA; zA = (zA > 0.0f) ? zA : NEG_SLOPE * zA;
    float zB = g_asrc[jB] + adB; zB = (zB > 0.0f) ? zB : NEG_SLOPE * zB;
    float esA = __expf(zA), esB = __expf(zB);
    float invA = 1.0f / (pA + esA);
    float invB = 1.0f / (pB + esB);

    float4 hA = reinterpret_cast<const float4*>(&g_h[jA * C_OUT])[lane];
    float4 hB = reinterpret_cast<const float4*>(&g_h[jB * C_OUT])[lane];
    float4 accA0 = make_float4(esA * hA.x, esA * hA.y, esA * hA.z, esA * hA.w);
    float4 accA1 = make_float4(0.f, 0.f, 0.f, 0.f);
    float4 accB0 = make_float4(esB * hB.x, esB * hB.y, esB * hB.z, esB * hB.w);
    float4 accB1 = make_float4(0.f, 0.f, 0.f, 0.f);

    const uint2* h16 = reinterpret_cast<const uint2*>(g_h16);   // 32 uint2/row

    int dA = 0, dB = 0;
    while (dA < cA4 || dB < cB4) {
        bool doA = dA < cA4;
        bool doB = dB < cB4;
        float2 qa0, qa1, qa2, qa3, qb0, qb1, qb2, qb3;
        uint2  pa0, pa1, pa2, pa3, pb0, pb1, pb2, pb3;
        if (doA) {
            qa0 = sq[sA][dA];     qa1 = sq[sA][dA + 1];
            qa2 = sq[sA][dA + 2]; qa3 = sq[sA][dA + 3];
            pa0 = h16[__float_as_int(qa0.y) * 32 + lane];
            pa1 = h16[__float_as_int(qa1.y) * 32 + lane];
            pa2 = h16[__float_as_int(qa2.y) * 32 + lane];
            pa3 = h16[__float_as_int(qa3.y) * 32 + lane];
        }
        if (doB) {
            qb0 = sq[sB][dB];     qb1 = sq[sB][dB + 1];
            qb2 = sq[sB][dB + 2]; qb3 = sq[sB][dB + 3];
            pb0 = h16[__float_as_int(qb0.y) * 32 + lane];
            pb1 = h16[__float_as_int(qb1.y) * 32 + lane];
            pb2 = h16[__float_as_int(qb2.y) * 32 + lane];
            pb3 = h16[__float_as_int(qb3.y) * 32 + lane];
        }
        if (doA) {
            fma_h16(accA0, qa0.x, pa0);
            fma_h16(accA1, qa1.x, pa1);
            fma_h16(accA0, qa2.x, pa2);
            fma_h16(accA1, qa3.x, pa3);
            dA += 4;
        }
        if (doB) {
            fma_h16(accB0, qb0.x, pb0);
            fma_h16(accB1, qb1.x, pb1);
            fma_h16(accB0, qb2.x, pb2);
            fma_h16(accB1, qb3.x, pb3);
            dB += 4;
        }
    }

    float4 bv = reinterpret_cast<const float4*>(bias)[lane];
    float4 oA, oB;
    oA.x = (accA0.x + accA1.x) * invA + bv.x;
    oA.y = (accA0.y + accA1.y) * invA + bv.y;
    oA.z = (accA0.z + accA1.z) * invA + bv.z;
    oA.w = (accA0.w + accA1.w) * invA + bv.w;
    oB.x = (accB0.x + accB1.x) * invB + bv.x;
    oB.y = (accB0.y + accB1.y) * invB + bv.y;
    oB.z = (accB0.z + accB1.z) * invB + bv.z;
    oB.w = (accB0.w + accB1.w) * invB + bv.w;
    reinterpret_cast<float4*>(&out[jA * C_OUT])[lane] = oA;
    reinterpret_cast<float4*>(&out[jB * C_OUT])[lane] = oB;
}

// ---------------------------------------------------------------------
extern "C" void kernel_launch(void* const* d_in, const int* in_sizes, int n_in,
                              void* d_out, int out_size) {
    const float* x       = (const float*)d_in[0];
    const float* adj     = (const float*)d_in[1];
    const float* W       = (const float*)d_in[2];
    const float* att_src = (const float*)d_in[3];
    const float* att_dst = (const float*)d_in[4];
    const float* bias    = (const float*)d_in[5];
    float* out = (float*)d_out;

    fused_front_kernel<<<GEMM_BLOCKS + SCAN_BLOCKS, 256>>>(x, W, adj, att_src, att_dst);
    aggregate_kernel<<<N_NODES / 8, 128>>>(bias, out);
}